// round 1
// baseline (speedup 1.0000x reference)
#include <cuda_runtime.h>
#include <cuda_bf16.h>
#include <cstddef>

// ---------------------------------------------------------------------------
// Transformer forward: L=4 layers, B=4, N=2048, D=512, H=8, HD=64, fp32.
// Round 0: correct SIMT baseline. h lives in d_out (in-place residual stream).
// ---------------------------------------------------------------------------

#define L_LAYERS 4
#define B_SZ     4
#define N_SEQ    2048
#define D_MODEL  512
#define H_HEADS  8
#define HD_DIM   64
#define TOK      (B_SZ * N_SEQ)            // 8192
#define SZ_ACT   ((size_t)TOK * D_MODEL)   // 4194304 floats
#define SZ_S     ((size_t)B_SZ * H_HEADS * N_SEQ * N_SEQ)  // 134217728 floats
#define LN_EPS   1e-5f
#define ATTN_SCALE 0.044194173824159216f   // 512^-0.5 (reference uses D, not HD)

// scratch: y | q | k | v | tmp | S
__device__ float g_scratch[5 * SZ_ACT + SZ_S];

// ---------------------------------------------------------------------------
// LayerNorm: one block per row (D=512), 128 threads x float4
// ---------------------------------------------------------------------------
__global__ __launch_bounds__(128) void ln_kernel(
    const float* __restrict__ h, const float* __restrict__ g,
    const float* __restrict__ b, float* __restrict__ y)
{
    int row = blockIdx.x;
    int tid = threadIdx.x;
    const float4* hv = (const float4*)(h + (size_t)row * D_MODEL);
    float4 v = hv[tid];
    float s  = v.x + v.y + v.z + v.w;
    float ss = v.x*v.x + v.y*v.y + v.z*v.z + v.w*v.w;
    #pragma unroll
    for (int o = 16; o > 0; o >>= 1) {
        s  += __shfl_xor_sync(0xffffffffu, s,  o);
        ss += __shfl_xor_sync(0xffffffffu, ss, o);
    }
    __shared__ float sm[4], sm2[4];
    int w = tid >> 5;
    if ((tid & 31) == 0) { sm[w] = s; sm2[w] = ss; }
    __syncthreads();
    s  = sm[0] + sm[1] + sm[2] + sm[3];
    ss = sm2[0] + sm2[1] + sm2[2] + sm2[3];
    float mean = s * (1.0f / D_MODEL);
    float var  = ss * (1.0f / D_MODEL) - mean * mean;
    float r    = rsqrtf(var + LN_EPS);
    float4 gv = ((const float4*)g)[tid];
    float4 bv = ((const float4*)b)[tid];
    float4 o4;
    o4.x = (v.x - mean) * r * gv.x + bv.x;
    o4.y = (v.y - mean) * r * gv.y + bv.y;
    o4.z = (v.z - mean) * r * gv.z + bv.z;
    o4.w = (v.w - mean) * r * gv.w + bv.w;
    ((float4*)(y + (size_t)row * D_MODEL))[tid] = o4;
}

// ---------------------------------------------------------------------------
// Row softmax over S: one block per row of 2048, 256 threads x 8 elems
// ---------------------------------------------------------------------------
__global__ __launch_bounds__(256) void softmax_kernel(float* __restrict__ S)
{
    float* p = S + (size_t)blockIdx.x * N_SEQ;
    int tid = threadIdx.x;
    float4 a = ((const float4*)p)[tid];
    float4 c = ((const float4*)p)[tid + 256];
    float mx = fmaxf(fmaxf(fmaxf(a.x, a.y), fmaxf(a.z, a.w)),
                     fmaxf(fmaxf(c.x, c.y), fmaxf(c.z, c.w)));
    #pragma unroll
    for (int o = 16; o > 0; o >>= 1) mx = fmaxf(mx, __shfl_xor_sync(0xffffffffu, mx, o));
    __shared__ float sm[8];
    int w = tid >> 5;
    if ((tid & 31) == 0) sm[w] = mx;
    __syncthreads();
    mx = sm[0];
    #pragma unroll
    for (int i = 1; i < 8; i++) mx = fmaxf(mx, sm[i]);

    a.x = __expf(a.x - mx); a.y = __expf(a.y - mx);
    a.z = __expf(a.z - mx); a.w = __expf(a.w - mx);
    c.x = __expf(c.x - mx); c.y = __expf(c.y - mx);
    c.z = __expf(c.z - mx); c.w = __expf(c.w - mx);

    float s = a.x + a.y + a.z + a.w + c.x + c.y + c.z + c.w;
    #pragma unroll
    for (int o = 16; o > 0; o >>= 1) s += __shfl_xor_sync(0xffffffffu, s, o);
    __shared__ float sm2[8];
    if ((tid & 31) == 0) sm2[w] = s;
    __syncthreads();
    s = sm2[0];
    #pragma unroll
    for (int i = 1; i < 8; i++) s += sm2[i];
    float inv = 1.0f / s;
    a.x *= inv; a.y *= inv; a.z *= inv; a.w *= inv;
    c.x *= inv; c.y *= inv; c.z *= inv; c.w *= inv;
    ((float4*)p)[tid]       = a;
    ((float4*)p)[tid + 256] = c;
}

// ---------------------------------------------------------------------------
// Generic tiled SGEMM with fused epilogues.
//   C[m,n] = alpha * sum_k A[m,k] * B'[k,n]     (B' = B or B^T per TRANSB)
//   EPI: 0 = store, 1 = +bias, 2 = +bias then GELU, 3 = +bias then +C (residual)
// Batch (blockIdx.z): offsets = (z/H)*s1 + (z%H)*s2 per operand.
// All tile dims assumed to divide problem dims exactly.
// ---------------------------------------------------------------------------
__device__ __forceinline__ float gelu_exact(float x) {
    return 0.5f * x * (1.0f + erff(x * 0.7071067811865476f));
}

template<int BM, int BN, int BK, int TM, int TN, bool TRANSB, int EPI>
__global__ __launch_bounds__((BM/TM)*(BN/TN)) void gemm_kernel(
    const float* __restrict__ A, int lda, long long sA1, long long sA2,
    const float* __restrict__ B, int ldb, long long sB1, long long sB2,
    float* __restrict__ C, int ldc, long long sC1, long long sC2,
    const float* __restrict__ bias, int K, float alpha)
{
    constexpr int THREADS = (BM/TM)*(BN/TN);
    __shared__ float As[BK][BM];
    __shared__ float Bs[BK][BN];

    int z  = blockIdx.z;
    int zb = z / H_HEADS, zh = z % H_HEADS;
    A += zb * sA1 + zh * sA2;
    B += zb * sB1 + zh * sB2;
    C += zb * sC1 + zh * sC2;

    int m0 = blockIdx.y * BM;
    int n0 = blockIdx.x * BN;
    int tid = threadIdx.x;
    int tx = tid % (BN/TN);
    int ty = tid / (BN/TN);

    float acc[TM][TN];
    #pragma unroll
    for (int i = 0; i < TM; i++)
        #pragma unroll
        for (int j = 0; j < TN; j++) acc[i][j] = 0.0f;

    for (int k0 = 0; k0 < K; k0 += BK) {
        #pragma unroll
        for (int i = tid; i < BM*BK; i += THREADS) {
            int m = i / BK, kk = i % BK;
            As[kk][m] = A[(size_t)(m0 + m) * lda + (k0 + kk)];
        }
        if (!TRANSB) {
            #pragma unroll
            for (int i = tid; i < BK*BN; i += THREADS) {
                int kk = i / BN, n = i % BN;
                Bs[kk][n] = B[(size_t)(k0 + kk) * ldb + (n0 + n)];
            }
        } else {
            #pragma unroll
            for (int i = tid; i < BK*BN; i += THREADS) {
                int n = i / BK, kk = i % BK;
                Bs[kk][n] = B[(size_t)(n0 + n) * ldb + (k0 + kk)];
            }
        }
        __syncthreads();

        #pragma unroll
        for (int kk = 0; kk < BK; kk++) {
            float rA[TM], rB[TN];
            #pragma unroll
            for (int i = 0; i < TM; i++) rA[i] = As[kk][ty*TM + i];
            #pragma unroll
            for (int j = 0; j < TN; j++) rB[j] = Bs[kk][tx*TN + j];
            #pragma unroll
            for (int i = 0; i < TM; i++)
                #pragma unroll
                for (int j = 0; j < TN; j++)
                    acc[i][j] += rA[i] * rB[j];
        }
        __syncthreads();
    }

    #pragma unroll
    for (int i = 0; i < TM; i++) {
        int m = m0 + ty*TM + i;
        #pragma unroll
        for (int j = 0; j < TN; j++) {
            int n = n0 + tx*TN + j;
            float val = acc[i][j] * alpha;
            if (EPI == 1 || EPI == 2 || EPI == 3) val += bias[n];
            if (EPI == 2) val = gelu_exact(val);
            size_t off = (size_t)m * ldc + n;
            if (EPI == 3) val += C[off];
            C[off] = val;
        }
    }
}

// ---------------------------------------------------------------------------
// Host orchestration (graph-capturable: only kernel launches + async d2d copy)
// ---------------------------------------------------------------------------
extern "C" void kernel_launch(void* const* d_in, const int* in_sizes, int n_in,
                              void* d_out, int out_size)
{
    const float* x     = (const float*)d_in[0];
    const float* Wq    = (const float*)d_in[1];
    const float* Wk    = (const float*)d_in[2];
    const float* Wv    = (const float*)d_in[3];
    const float* Wo    = (const float*)d_in[4];
    const float* bo    = (const float*)d_in[5];
    const float* ln1g  = (const float*)d_in[6];
    const float* ln1b  = (const float*)d_in[7];
    const float* W1    = (const float*)d_in[8];
    const float* b1    = (const float*)d_in[9];
    const float* W2    = (const float*)d_in[10];
    const float* b2    = (const float*)d_in[11];
    const float* ln2g  = (const float*)d_in[12];
    const float* ln2b  = (const float*)d_in[13];

    float* h = (float*)d_out;

    float* scratch = nullptr;
    cudaGetSymbolAddress((void**)&scratch, g_scratch);
    float* y    = scratch + 0 * SZ_ACT;
    float* q    = scratch + 1 * SZ_ACT;
    float* kbuf = scratch + 2 * SZ_ACT;
    float* v    = scratch + 3 * SZ_ACT;
    float* tmp  = scratch + 4 * SZ_ACT;
    float* S    = scratch + 5 * SZ_ACT;

    // residual stream starts as x
    cudaMemcpyAsync(h, x, SZ_ACT * sizeof(float), cudaMemcpyDeviceToDevice, 0);

    const long long DD  = (long long)D_MODEL * D_MODEL;
    const long long sND = (long long)N_SEQ * D_MODEL;   // per-batch act stride
    const long long sNN = (long long)N_SEQ * N_SEQ;     // per-head S stride

    dim3 gProj(D_MODEL/128, TOK/128, 1);                 // (4, 64)
    dim3 gScore(N_SEQ/128, N_SEQ/128, B_SZ*H_HEADS);     // (16, 16, 32)
    dim3 gAV(HD_DIM/64, N_SEQ/64, B_SZ*H_HEADS);         // (1, 32, 32)

    for (int l = 0; l < L_LAYERS; l++) {
        const float* wq  = Wq + (size_t)l * DD;
        const float* wk  = Wk + (size_t)l * DD;
        const float* wv  = Wv + (size_t)l * DD;
        const float* wo  = Wo + (size_t)l * DD;
        const float* w1  = W1 + (size_t)l * DD;
        const float* w2  = W2 + (size_t)l * DD;
        const float* bo_ = bo + (size_t)l * D_MODEL;
        const float* b1_ = b1 + (size_t)l * D_MODEL;
        const float* b2_ = b2 + (size_t)l * D_MODEL;

        // y = LN1(h)
        ln_kernel<<<TOK, 128>>>(h, ln1g + (size_t)l*D_MODEL, ln1b + (size_t)l*D_MODEL, y);

        // q/k/v = y @ W{q,k,v}
        gemm_kernel<128,128,8,8,8,false,0><<<gProj,256>>>(
            y, D_MODEL, 0, 0, wq, D_MODEL, 0, 0, q, D_MODEL, 0, 0, nullptr, D_MODEL, 1.0f);
        gemm_kernel<128,128,8,8,8,false,0><<<gProj,256>>>(
            y, D_MODEL, 0, 0, wk, D_MODEL, 0, 0, kbuf, D_MODEL, 0, 0, nullptr, D_MODEL, 1.0f);
        gemm_kernel<128,128,8,8,8,false,0><<<gProj,256>>>(
            y, D_MODEL, 0, 0, wv, D_MODEL, 0, 0, v, D_MODEL, 0, 0, nullptr, D_MODEL, 1.0f);

        // S = scale * q @ k^T   (batched over b,h)
        gemm_kernel<128,128,8,8,8,true,0><<<gScore,256>>>(
            q,    D_MODEL, sND, HD_DIM,
            kbuf, D_MODEL, sND, HD_DIM,
            S,    N_SEQ,   (long long)H_HEADS * sNN, sNN,
            nullptr, HD_DIM, ATTN_SCALE);

        // softmax rows
        softmax_kernel<<<B_SZ*H_HEADS*N_SEQ, 256>>>(S);

        // tmp = S @ v
        gemm_kernel<64,64,16,4,4,false,0><<<gAV,256>>>(
            S,   N_SEQ,   (long long)H_HEADS * sNN, sNN,
            v,   D_MODEL, sND, HD_DIM,
            tmp, D_MODEL, sND, HD_DIM,
            nullptr, N_SEQ, 1.0f);

        // h = h + tmp @ Wo + bo
        gemm_kernel<128,128,8,8,8,false,3><<<gProj,256>>>(
            tmp, D_MODEL, 0, 0, wo, D_MODEL, 0, 0, h, D_MODEL, 0, 0, bo_, D_MODEL, 1.0f);

        // y = LN2(h)
        ln_kernel<<<TOK, 128>>>(h, ln2g + (size_t)l*D_MODEL, ln2b + (size_t)l*D_MODEL, y);

        // tmp = gelu(y @ W1 + b1)
        gemm_kernel<128,128,8,8,8,false,2><<<gProj,256>>>(
            y, D_MODEL, 0, 0, w1, D_MODEL, 0, 0, tmp, D_MODEL, 0, 0, b1_, D_MODEL, 1.0f);

        // h = h + tmp @ W2 + b2
        gemm_kernel<128,128,8,8,8,false,3><<<gProj,256>>>(
            tmp, D_MODEL, 0, 0, w2, D_MODEL, 0, 0, h, D_MODEL, 0, 0, b2_, D_MODEL, 1.0f);
    }
}

// round 2
// speedup vs baseline: 2.7444x; 2.7444x over previous
#include <cuda_runtime.h>
#include <cuda_bf16.h>
#include <cstddef>

// ---------------------------------------------------------------------------
// Transformer forward: L=4, B=4, N=2048, D=512, H=8, HD=64, fp32 in/out.
// Round 2: all GEMMs on tensor pipe via mma.sync.m16n8k8.tf32 (fp32 accum).
// ---------------------------------------------------------------------------

#define L_LAYERS 4
#define B_SZ     4
#define N_SEQ    2048
#define D_MODEL  512
#define H_HEADS  8
#define HD_DIM   64
#define TOK      (B_SZ * N_SEQ)            // 8192
#define SZ_ACT   ((size_t)TOK * D_MODEL)   // 4194304 floats
#define SZ_S     ((size_t)B_SZ * H_HEADS * N_SEQ * N_SEQ)  // 134217728 floats
#define LN_EPS   1e-5f
#define ATTN_SCALE 0.044194173824159216f   // 512^-0.5 (reference scales by D)

// scratch: y | q | k | v | tmp | S
__device__ float g_scratch[5 * SZ_ACT + SZ_S];

// ---------------------------------------------------------------------------
// LayerNorm: one block per row (D=512), 128 threads x float4
// ---------------------------------------------------------------------------
__global__ __launch_bounds__(128) void ln_kernel(
    const float* __restrict__ h, const float* __restrict__ g,
    const float* __restrict__ b, float* __restrict__ y)
{
    int row = blockIdx.x;
    int tid = threadIdx.x;
    const float4* hv = (const float4*)(h + (size_t)row * D_MODEL);
    float4 v = hv[tid];
    float s  = v.x + v.y + v.z + v.w;
    float ss = v.x*v.x + v.y*v.y + v.z*v.z + v.w*v.w;
    #pragma unroll
    for (int o = 16; o > 0; o >>= 1) {
        s  += __shfl_xor_sync(0xffffffffu, s,  o);
        ss += __shfl_xor_sync(0xffffffffu, ss, o);
    }
    __shared__ float sm[4], sm2[4];
    int w = tid >> 5;
    if ((tid & 31) == 0) { sm[w] = s; sm2[w] = ss; }
    __syncthreads();
    s  = sm[0] + sm[1] + sm[2] + sm[3];
    ss = sm2[0] + sm2[1] + sm2[2] + sm2[3];
    float mean = s * (1.0f / D_MODEL);
    float var  = ss * (1.0f / D_MODEL) - mean * mean;
    float r    = rsqrtf(var + LN_EPS);
    float4 gv = ((const float4*)g)[tid];
    float4 bv = ((const float4*)b)[tid];
    float4 o4;
    o4.x = (v.x - mean) * r * gv.x + bv.x;
    o4.y = (v.y - mean) * r * gv.y + bv.y;
    o4.z = (v.z - mean) * r * gv.z + bv.z;
    o4.w = (v.w - mean) * r * gv.w + bv.w;
    ((float4*)(y + (size_t)row * D_MODEL))[tid] = o4;
}

// ---------------------------------------------------------------------------
// Row softmax over S: one block per row of 2048, 256 threads x 8 elems
// ---------------------------------------------------------------------------
__global__ __launch_bounds__(256) void softmax_kernel(float* __restrict__ S)
{
    float* p = S + (size_t)blockIdx.x * N_SEQ;
    int tid = threadIdx.x;
    float4 a = ((const float4*)p)[tid];
    float4 c = ((const float4*)p)[tid + 256];
    float mx = fmaxf(fmaxf(fmaxf(a.x, a.y), fmaxf(a.z, a.w)),
                     fmaxf(fmaxf(c.x, c.y), fmaxf(c.z, c.w)));
    #pragma unroll
    for (int o = 16; o > 0; o >>= 1) mx = fmaxf(mx, __shfl_xor_sync(0xffffffffu, mx, o));
    __shared__ float sm[8];
    int w = tid >> 5;
    if ((tid & 31) == 0) sm[w] = mx;
    __syncthreads();
    mx = sm[0];
    #pragma unroll
    for (int i = 1; i < 8; i++) mx = fmaxf(mx, sm[i]);

    a.x = __expf(a.x - mx); a.y = __expf(a.y - mx);
    a.z = __expf(a.z - mx); a.w = __expf(a.w - mx);
    c.x = __expf(c.x - mx); c.y = __expf(c.y - mx);
    c.z = __expf(c.z - mx); c.w = __expf(c.w - mx);

    float s = a.x + a.y + a.z + a.w + c.x + c.y + c.z + c.w;
    #pragma unroll
    for (int o = 16; o > 0; o >>= 1) s += __shfl_xor_sync(0xffffffffu, s, o);
    __shared__ float sm2[8];
    if ((tid & 31) == 0) sm2[w] = s;
    __syncthreads();
    s = sm2[0];
    #pragma unroll
    for (int i = 1; i < 8; i++) s += sm2[i];
    float inv = 1.0f / s;
    a.x *= inv; a.y *= inv; a.z *= inv; a.w *= inv;
    c.x *= inv; c.y *= inv; c.z *= inv; c.w *= inv;
    ((float4*)p)[tid]       = a;
    ((float4*)p)[tid + 256] = c;
}

// ---------------------------------------------------------------------------
// Tensor-core GEMM via mma.sync.m16n8k8.tf32 (fp32 accumulate).
//   C[m,n] = alpha * sum_k A[m,k] * B'[k,n]   (B' = B or B^T per TRANSB)
//   EPI: 0 = store, 1 = +bias, 2 = +bias,GELU, 3 = +bias,+C (residual)
// Block tile BM x BN x 16, 8 warps (2x4), warp tile (BM/2)x(BN/4).
// Double-buffered smem, register prefetch, 1 syncthreads per K-iter.
// ---------------------------------------------------------------------------
__device__ __forceinline__ float gelu_exact(float x) {
    return 0.5f * x * (1.0f + erff(x * 0.7071067811865476f));
}

__device__ __forceinline__ unsigned f2tf32(float f) {
    unsigned u;
    asm("cvt.rna.tf32.f32 %0, %1;" : "=r"(u) : "f"(f));
    return u;
}

__device__ __forceinline__ void mma_tf32(float c[4],
    unsigned a0, unsigned a1, unsigned a2, unsigned a3,
    unsigned b0, unsigned b1)
{
    asm volatile(
        "mma.sync.aligned.m16n8k8.row.col.f32.tf32.tf32.f32 "
        "{%0,%1,%2,%3}, {%4,%5,%6,%7}, {%8,%9}, {%0,%1,%2,%3};\n"
        : "+f"(c[0]), "+f"(c[1]), "+f"(c[2]), "+f"(c[3])
        : "r"(a0), "r"(a1), "r"(a2), "r"(a3), "r"(b0), "r"(b1));
}

template<int BM, int BN, bool TRANSB, int EPI>
__global__ __launch_bounds__(256) void mma_gemm(
    const float* __restrict__ A, int lda, long long sA1, long long sA2,
    const float* __restrict__ B, int ldb, long long sB1, long long sB2,
    float* __restrict__ C, int ldc, long long sC1, long long sC2,
    const float* __restrict__ bias, int K, float alpha)
{
    constexpr int BK   = 16;
    constexpr int A_F4 = BM * BK / 4;          // float4 count per A tile
    constexpr int B_F4 = BK * BN / 4;
    constexpr int A_PT = A_F4 / 256;           // float4 per thread
    constexpr int B_PT = B_F4 / 256;
    constexpr int MI   = (BM / 2) / 16;        // mma tiles per warp, M
    constexpr int NI   = (BN / 4) / 8;         // mma tiles per warp, N

    __shared__ float As[2][BM][BK + 4];
    __shared__ float Bs[2][BK][BN + 4];

    int z  = blockIdx.z;
    int zb = z / H_HEADS, zh = z % H_HEADS;
    A += zb * sA1 + zh * sA2;
    B += zb * sB1 + zh * sB2;
    C += zb * sC1 + zh * sC2;

    const int m0   = blockIdx.y * BM;
    const int n0   = blockIdx.x * BN;
    const int tid  = threadIdx.x;
    const int warp = tid >> 5, lane = tid & 31;
    const int wm   = warp & 1, wn = warp >> 1;  // 2 x 4 warp grid
    const int g    = lane >> 2, q = lane & 3;

    float4 ra[A_PT], rb[B_PT];

    float acc[MI][NI][4];
    #pragma unroll
    for (int mi = 0; mi < MI; mi++)
        #pragma unroll
        for (int ni = 0; ni < NI; ni++)
            #pragma unroll
            for (int j = 0; j < 4; j++) acc[mi][ni][j] = 0.0f;

    auto loadA = [&](int k0) {
        #pragma unroll
        for (int p = 0; p < A_PT; p++) {
            int i = tid + p * 256;
            int r = i >> 2, c = (i & 3) << 2;              // BK/4 == 4
            ra[p] = *reinterpret_cast<const float4*>(
                A + (size_t)(m0 + r) * lda + k0 + c);
        }
    };
    auto storeA = [&](int buf) {
        #pragma unroll
        for (int p = 0; p < A_PT; p++) {
            int i = tid + p * 256;
            int r = i >> 2, c = (i & 3) << 2;
            As[buf][r][c + 0] = __uint_as_float(f2tf32(ra[p].x));
            As[buf][r][c + 1] = __uint_as_float(f2tf32(ra[p].y));
            As[buf][r][c + 2] = __uint_as_float(f2tf32(ra[p].z));
            As[buf][r][c + 3] = __uint_as_float(f2tf32(ra[p].w));
        }
    };
    auto loadB = [&](int k0) {
        #pragma unroll
        for (int p = 0; p < B_PT; p++) {
            int i = tid + p * 256;
            if (!TRANSB) {
                int kk = i / (BN / 4), c = (i % (BN / 4)) << 2;
                rb[p] = *reinterpret_cast<const float4*>(
                    B + (size_t)(k0 + kk) * ldb + n0 + c);
            } else {
                int n = i >> 2, c = (i & 3) << 2;
                rb[p] = *reinterpret_cast<const float4*>(
                    B + (size_t)(n0 + n) * ldb + k0 + c);
            }
        }
    };
    auto storeB = [&](int buf) {
        #pragma unroll
        for (int p = 0; p < B_PT; p++) {
            int i = tid + p * 256;
            if (!TRANSB) {
                int kk = i / (BN / 4), c = (i % (BN / 4)) << 2;
                Bs[buf][kk][c + 0] = __uint_as_float(f2tf32(rb[p].x));
                Bs[buf][kk][c + 1] = __uint_as_float(f2tf32(rb[p].y));
                Bs[buf][kk][c + 2] = __uint_as_float(f2tf32(rb[p].z));
                Bs[buf][kk][c + 3] = __uint_as_float(f2tf32(rb[p].w));
            } else {
                int n = i >> 2, c = (i & 3) << 2;
                Bs[buf][c + 0][n] = __uint_as_float(f2tf32(rb[p].x));
                Bs[buf][c + 1][n] = __uint_as_float(f2tf32(rb[p].y));
                Bs[buf][c + 2][n] = __uint_as_float(f2tf32(rb[p].z));
                Bs[buf][c + 3][n] = __uint_as_float(f2tf32(rb[p].w));
            }
        }
    };
    auto compute = [&](int buf) {
        #pragma unroll
        for (int ks = 0; ks < 2; ks++) {
            unsigned af[MI][4], bf[NI][2];
            #pragma unroll
            for (int mi = 0; mi < MI; mi++) {
                int m = wm * (BM / 2) + mi * 16;
                af[mi][0] = __float_as_uint(As[buf][m + g    ][ks * 8 + q    ]);
                af[mi][1] = __float_as_uint(As[buf][m + g + 8][ks * 8 + q    ]);
                af[mi][2] = __float_as_uint(As[buf][m + g    ][ks * 8 + q + 4]);
                af[mi][3] = __float_as_uint(As[buf][m + g + 8][ks * 8 + q + 4]);
            }
            #pragma unroll
            for (int ni = 0; ni < NI; ni++) {
                int n = wn * (BN / 4) + ni * 8;
                bf[ni][0] = __float_as_uint(Bs[buf][ks * 8 + q    ][n + g]);
                bf[ni][1] = __float_as_uint(Bs[buf][ks * 8 + q + 4][n + g]);
            }
            #pragma unroll
            for (int mi = 0; mi < MI; mi++)
                #pragma unroll
                for (int ni = 0; ni < NI; ni++)
                    mma_tf32(acc[mi][ni], af[mi][0], af[mi][1], af[mi][2],
                             af[mi][3], bf[ni][0], bf[ni][1]);
        }
    };

    const int nIter = K / BK;
    loadA(0); loadB(0);
    storeA(0); storeB(0);
    __syncthreads();

    int buf = 0;
    for (int it = 0; it < nIter; it++) {
        if (it + 1 < nIter) { loadA((it + 1) * BK); loadB((it + 1) * BK); }
        compute(buf);
        if (it + 1 < nIter) {
            storeA(buf ^ 1); storeB(buf ^ 1);
            __syncthreads();
            buf ^= 1;
        }
    }

    // ---- epilogue ----
    auto emit = [&](int m, int n, float v0, float v1) {
        v0 *= alpha; v1 *= alpha;
        if (EPI == 1 || EPI == 2 || EPI == 3) { v0 += bias[n]; v1 += bias[n + 1]; }
        if (EPI == 2) { v0 = gelu_exact(v0); v1 = gelu_exact(v1); }
        float2* p = reinterpret_cast<float2*>(C + (size_t)m * ldc + n);
        if (EPI == 3) { float2 o = *p; v0 += o.x; v1 += o.y; }
        *p = make_float2(v0, v1);
    };

    #pragma unroll
    for (int mi = 0; mi < MI; mi++) {
        int m = m0 + wm * (BM / 2) + mi * 16 + g;
        #pragma unroll
        for (int ni = 0; ni < NI; ni++) {
            int n = n0 + wn * (BN / 4) + ni * 8 + q * 2;
            emit(m,     n, acc[mi][ni][0], acc[mi][ni][1]);
            emit(m + 8, n, acc[mi][ni][2], acc[mi][ni][3]);
        }
    }
}

// ---------------------------------------------------------------------------
// Host orchestration (graph-capturable: only kernel launches + async d2d copy)
// ---------------------------------------------------------------------------
extern "C" void kernel_launch(void* const* d_in, const int* in_sizes, int n_in,
                              void* d_out, int out_size)
{
    const float* x     = (const float*)d_in[0];
    const float* Wq    = (const float*)d_in[1];
    const float* Wk    = (const float*)d_in[2];
    const float* Wv    = (const float*)d_in[3];
    const float* Wo    = (const float*)d_in[4];
    const float* bo    = (const float*)d_in[5];
    const float* ln1g  = (const float*)d_in[6];
    const float* ln1b  = (const float*)d_in[7];
    const float* W1    = (const float*)d_in[8];
    const float* b1    = (const float*)d_in[9];
    const float* W2    = (const float*)d_in[10];
    const float* b2    = (const float*)d_in[11];
    const float* ln2g  = (const float*)d_in[12];
    const float* ln2b  = (const float*)d_in[13];

    float* h = (float*)d_out;

    float* scratch = nullptr;
    cudaGetSymbolAddress((void**)&scratch, g_scratch);
    float* y    = scratch + 0 * SZ_ACT;
    float* q    = scratch + 1 * SZ_ACT;
    float* kbuf = scratch + 2 * SZ_ACT;
    float* v    = scratch + 3 * SZ_ACT;
    float* tmp  = scratch + 4 * SZ_ACT;
    float* S    = scratch + 5 * SZ_ACT;

    // residual stream starts as x
    cudaMemcpyAsync(h, x, SZ_ACT * sizeof(float), cudaMemcpyDeviceToDevice, 0);

    const long long DD  = (long long)D_MODEL * D_MODEL;
    const long long sND = (long long)N_SEQ * D_MODEL;   // per-batch act stride
    const long long sNN = (long long)N_SEQ * N_SEQ;     // per-head S stride

    dim3 gProj(D_MODEL / 128, TOK / 128, 1);             // (4, 64)
    dim3 gScore(N_SEQ / 128, N_SEQ / 128, B_SZ*H_HEADS); // (16, 16, 32)
    dim3 gAV(1, N_SEQ / 128, B_SZ * H_HEADS);            // (1, 16, 32)

    for (int l = 0; l < L_LAYERS; l++) {
        const float* wq  = Wq + (size_t)l * DD;
        const float* wk  = Wk + (size_t)l * DD;
        const float* wv  = Wv + (size_t)l * DD;
        const float* wo  = Wo + (size_t)l * DD;
        const float* w1  = W1 + (size_t)l * DD;
        const float* w2  = W2 + (size_t)l * DD;
        const float* bo_ = bo + (size_t)l * D_MODEL;
        const float* b1_ = b1 + (size_t)l * D_MODEL;
        const float* b2_ = b2 + (size_t)l * D_MODEL;

        // y = LN1(h)
        ln_kernel<<<TOK, 128>>>(h, ln1g + (size_t)l*D_MODEL, ln1b + (size_t)l*D_MODEL, y);

        // q/k/v = y @ W{q,k,v}
        mma_gemm<128,128,false,0><<<gProj,256>>>(
            y, D_MODEL, 0, 0, wq, D_MODEL, 0, 0, q, D_MODEL, 0, 0, nullptr, D_MODEL, 1.0f);
        mma_gemm<128,128,false,0><<<gProj,256>>>(
            y, D_MODEL, 0, 0, wk, D_MODEL, 0, 0, kbuf, D_MODEL, 0, 0, nullptr, D_MODEL, 1.0f);
        mma_gemm<128,128,false,0><<<gProj,256>>>(
            y, D_MODEL, 0, 0, wv, D_MODEL, 0, 0, v, D_MODEL, 0, 0, nullptr, D_MODEL, 1.0f);

        // S = scale * q @ k^T   (batched over b,h)
        mma_gemm<128,128,true,0><<<gScore,256>>>(
            q,    D_MODEL, sND, HD_DIM,
            kbuf, D_MODEL, sND, HD_DIM,
            S,    N_SEQ,   (long long)H_HEADS * sNN, sNN,
            nullptr, HD_DIM, ATTN_SCALE);

        // softmax rows
        softmax_kernel<<<B_SZ*H_HEADS*N_SEQ, 256>>>(S);

        // tmp = S @ v
        mma_gemm<128,64,false,0><<<gAV,256>>>(
            S,   N_SEQ,   (long long)H_HEADS * sNN, sNN,
            v,   D_MODEL, sND, HD_DIM,
            tmp, D_MODEL, sND, HD_DIM,
            nullptr, N_SEQ, 1.0f);

        // h = h + tmp @ Wo + bo
        mma_gemm<128,128,false,3><<<gProj,256>>>(
            tmp, D_MODEL, 0, 0, wo, D_MODEL, 0, 0, h, D_MODEL, 0, 0, bo_, D_MODEL, 1.0f);

        // y = LN2(h)
        ln_kernel<<<TOK, 128>>>(h, ln2g + (size_t)l*D_MODEL, ln2b + (size_t)l*D_MODEL, y);

        // tmp = gelu(y @ W1 + b1)
        mma_gemm<128,128,false,2><<<gProj,256>>>(
            y, D_MODEL, 0, 0, w1, D_MODEL, 0, 0, tmp, D_MODEL, 0, 0, b1_, D_MODEL, 1.0f);

        // h = h + tmp @ W2 + b2
        mma_gemm<128,128,false,3><<<gProj,256>>>(
            tmp, D_MODEL, 0, 0, w2, D_MODEL, 0, 0, h, D_MODEL, 0, 0, b2_, D_MODEL, 1.0f);
    }
}

// round 3
// speedup vs baseline: 2.7512x; 1.0025x over previous
#include <cuda_runtime.h>
#include <cuda_bf16.h>
#include <cstddef>

// ---------------------------------------------------------------------------
// Transformer forward: L=4, B=4, N=2048, D=512, H=8, HD=64, fp32 in/out.
// Round 2: all GEMMs on tensor pipe via mma.sync.m16n8k8.tf32 (fp32 accum).
// ---------------------------------------------------------------------------

#define L_LAYERS 4
#define B_SZ     4
#define N_SEQ    2048
#define D_MODEL  512
#define H_HEADS  8
#define HD_DIM   64
#define TOK      (B_SZ * N_SEQ)            // 8192
#define SZ_ACT   ((size_t)TOK * D_MODEL)   // 4194304 floats
#define SZ_S     ((size_t)B_SZ * H_HEADS * N_SEQ * N_SEQ)  // 134217728 floats
#define LN_EPS   1e-5f
#define ATTN_SCALE 0.044194173824159216f   // 512^-0.5 (reference scales by D)

// scratch: y | q | k | v | tmp | S
__device__ float g_scratch[5 * SZ_ACT + SZ_S];

// ---------------------------------------------------------------------------
// LayerNorm: one block per row (D=512), 128 threads x float4
// ---------------------------------------------------------------------------
__global__ __launch_bounds__(128) void ln_kernel(
    const float* __restrict__ h, const float* __restrict__ g,
    const float* __restrict__ b, float* __restrict__ y)
{
    int row = blockIdx.x;
    int tid = threadIdx.x;
    const float4* hv = (const float4*)(h + (size_t)row * D_MODEL);
    float4 v = hv[tid];
    float s  = v.x + v.y + v.z + v.w;
    float ss = v.x*v.x + v.y*v.y + v.z*v.z + v.w*v.w;
    #pragma unroll
    for (int o = 16; o > 0; o >>= 1) {
        s  += __shfl_xor_sync(0xffffffffu, s,  o);
        ss += __shfl_xor_sync(0xffffffffu, ss, o);
    }
    __shared__ float sm[4], sm2[4];
    int w = tid >> 5;
    if ((tid & 31) == 0) { sm[w] = s; sm2[w] = ss; }
    __syncthreads();
    s  = sm[0] + sm[1] + sm[2] + sm[3];
    ss = sm2[0] + sm2[1] + sm2[2] + sm2[3];
    float mean = s * (1.0f / D_MODEL);
    float var  = ss * (1.0f / D_MODEL) - mean * mean;
    float r    = rsqrtf(var + LN_EPS);
    float4 gv = ((const float4*)g)[tid];
    float4 bv = ((const float4*)b)[tid];
    float4 o4;
    o4.x = (v.x - mean) * r * gv.x + bv.x;
    o4.y = (v.y - mean) * r * gv.y + bv.y;
    o4.z = (v.z - mean) * r * gv.z + bv.z;
    o4.w = (v.w - mean) * r * gv.w + bv.w;
    ((float4*)(y + (size_t)row * D_MODEL))[tid] = o4;
}

// ---------------------------------------------------------------------------
// Row softmax over S: one block per row of 2048, 256 threads x 8 elems
// ---------------------------------------------------------------------------
__global__ __launch_bounds__(256) void softmax_kernel(float* __restrict__ S)
{
    float* p = S + (size_t)blockIdx.x * N_SEQ;
    int tid = threadIdx.x;
    float4 a = ((const float4*)p)[tid];
    float4 c = ((const float4*)p)[tid + 256];
    float mx = fmaxf(fmaxf(fmaxf(a.x, a.y), fmaxf(a.z, a.w)),
                     fmaxf(fmaxf(c.x, c.y), fmaxf(c.z, c.w)));
    #pragma unroll
    for (int o = 16; o > 0; o >>= 1) mx = fmaxf(mx, __shfl_xor_sync(0xffffffffu, mx, o));
    __shared__ float sm[8];
    int w = tid >> 5;
    if ((tid & 31) == 0) sm[w] = mx;
    __syncthreads();
    mx = sm[0];
    #pragma unroll
    for (int i = 1; i < 8; i++) mx = fmaxf(mx, sm[i]);

    a.x = __expf(a.x - mx); a.y = __expf(a.y - mx);
    a.z = __expf(a.z - mx); a.w = __expf(a.w - mx);
    c.x = __expf(c.x - mx); c.y = __expf(c.y - mx);
    c.z = __expf(c.z - mx); c.w = __expf(c.w - mx);

    float s = a.x + a.y + a.z + a.w + c.x + c.y + c.z + c.w;
    #pragma unroll
    for (int o = 16; o > 0; o >>= 1) s += __shfl_xor_sync(0xffffffffu, s, o);
    __shared__ float sm2[8];
    if ((tid & 31) == 0) sm2[w] = s;
    __syncthreads();
    s = sm2[0];
    #pragma unroll
    for (int i = 1; i < 8; i++) s += sm2[i];
    float inv = 1.0f / s;
    a.x *= inv; a.y *= inv; a.z *= inv; a.w *= inv;
    c.x *= inv; c.y *= inv; c.z *= inv; c.w *= inv;
    ((float4*)p)[tid]       = a;
    ((float4*)p)[tid + 256] = c;
}

// ---------------------------------------------------------------------------
// Tensor-core GEMM via mma.sync.m16n8k8.tf32 (fp32 accumulate).
//   C[m,n] = alpha * sum_k A[m,k] * B'[k,n]   (B' = B or B^T per TRANSB)
//   EPI: 0 = store, 1 = +bias, 2 = +bias,GELU, 3 = +bias,+C (residual)
// Block tile BM x BN x 16, 8 warps (2x4), warp tile (BM/2)x(BN/4).
// Double-buffered smem, register prefetch, 1 syncthreads per K-iter.
// ---------------------------------------------------------------------------
__device__ __forceinline__ float gelu_exact(float x) {
    return 0.5f * x * (1.0f + erff(x * 0.7071067811865476f));
}

__device__ __forceinline__ unsigned f2tf32(float f) {
    unsigned u;
    asm("cvt.rna.tf32.f32 %0, %1;" : "=r"(u) : "f"(f));
    return u;
}

__device__ __forceinline__ void mma_tf32(float c[4],
    unsigned a0, unsigned a1, unsigned a2, unsigned a3,
    unsigned b0, unsigned b1)
{
    asm volatile(
        "mma.sync.aligned.m16n8k8.row.col.f32.tf32.tf32.f32 "
        "{%0,%1,%2,%3}, {%4,%5,%6,%7}, {%8,%9}, {%0,%1,%2,%3};\n"
        : "+f"(c[0]), "+f"(c[1]), "+f"(c[2]), "+f"(c[3])
        : "r"(a0), "r"(a1), "r"(a2), "r"(a3), "r"(b0), "r"(b1));
}

template<int BM, int BN, bool TRANSB, int EPI>
__global__ __launch_bounds__(256) void mma_gemm(
    const float* __restrict__ A, int lda, long long sA1, long long sA2,
    const float* __restrict__ B, int ldb, long long sB1, long long sB2,
    float* __restrict__ C, int ldc, long long sC1, long long sC2,
    const float* __restrict__ bias, int K, float alpha)
{
    constexpr int BK   = 16;
    constexpr int A_F4 = BM * BK / 4;          // float4 count per A tile
    constexpr int B_F4 = BK * BN / 4;
    constexpr int A_PT = A_F4 / 256;           // float4 per thread
    constexpr int B_PT = B_F4 / 256;
    constexpr int MI   = (BM / 2) / 16;        // mma tiles per warp, M
    constexpr int NI   = (BN / 4) / 8;         // mma tiles per warp, N

    __shared__ float As[2][BM][BK + 4];
    __shared__ float Bs[2][BK][BN + 4];

    int z  = blockIdx.z;
    int zb = z / H_HEADS, zh = z % H_HEADS;
    A += zb * sA1 + zh * sA2;
    B += zb * sB1 + zh * sB2;
    C += zb * sC1 + zh * sC2;

    const int m0   = blockIdx.y * BM;
    const int n0   = blockIdx.x * BN;
    const int tid  = threadIdx.x;
    const int warp = tid >> 5, lane = tid & 31;
    const int wm   = warp & 1, wn = warp >> 1;  // 2 x 4 warp grid
    const int g    = lane >> 2, q = lane & 3;

    float4 ra[A_PT], rb[B_PT];

    float acc[MI][NI][4];
    #pragma unroll
    for (int mi = 0; mi < MI; mi++)
        #pragma unroll
        for (int ni = 0; ni < NI; ni++)
            #pragma unroll
            for (int j = 0; j < 4; j++) acc[mi][ni][j] = 0.0f;

    auto loadA = [&](int k0) {
        #pragma unroll
        for (int p = 0; p < A_PT; p++) {
            int i = tid + p * 256;
            int r = i >> 2, c = (i & 3) << 2;              // BK/4 == 4
            ra[p] = *reinterpret_cast<const float4*>(
                A + (size_t)(m0 + r) * lda + k0 + c);
        }
    };
    auto storeA = [&](int buf) {
        #pragma unroll
        for (int p = 0; p < A_PT; p++) {
            int i = tid + p * 256;
            int r = i >> 2, c = (i & 3) << 2;
            As[buf][r][c + 0] = __uint_as_float(f2tf32(ra[p].x));
            As[buf][r][c + 1] = __uint_as_float(f2tf32(ra[p].y));
            As[buf][r][c + 2] = __uint_as_float(f2tf32(ra[p].z));
            As[buf][r][c + 3] = __uint_as_float(f2tf32(ra[p].w));
        }
    };
    auto loadB = [&](int k0) {
        #pragma unroll
        for (int p = 0; p < B_PT; p++) {
            int i = tid + p * 256;
            if (!TRANSB) {
                int kk = i / (BN / 4), c = (i % (BN / 4)) << 2;
                rb[p] = *reinterpret_cast<const float4*>(
                    B + (size_t)(k0 + kk) * ldb + n0 + c);
            } else {
                int n = i >> 2, c = (i & 3) << 2;
                rb[p] = *reinterpret_cast<const float4*>(
                    B + (size_t)(n0 + n) * ldb + k0 + c);
            }
        }
    };
    auto storeB = [&](int buf) {
        #pragma unroll
        for (int p = 0; p < B_PT; p++) {
            int i = tid + p * 256;
            if (!TRANSB) {
                int kk = i / (BN / 4), c = (i % (BN / 4)) << 2;
                Bs[buf][kk][c + 0] = __uint_as_float(f2tf32(rb[p].x));
                Bs[buf][kk][c + 1] = __uint_as_float(f2tf32(rb[p].y));
                Bs[buf][kk][c + 2] = __uint_as_float(f2tf32(rb[p].z));
                Bs[buf][kk][c + 3] = __uint_as_float(f2tf32(rb[p].w));
            } else {
                int n = i >> 2, c = (i & 3) << 2;
                Bs[buf][c + 0][n] = __uint_as_float(f2tf32(rb[p].x));
                Bs[buf][c + 1][n] = __uint_as_float(f2tf32(rb[p].y));
                Bs[buf][c + 2][n] = __uint_as_float(f2tf32(rb[p].z));
                Bs[buf][c + 3][n] = __uint_as_float(f2tf32(rb[p].w));
            }
        }
    };
    auto compute = [&](int buf) {
        #pragma unroll
        for (int ks = 0; ks < 2; ks++) {
            unsigned af[MI][4], bf[NI][2];
            #pragma unroll
            for (int mi = 0; mi < MI; mi++) {
                int m = wm * (BM / 2) + mi * 16;
                af[mi][0] = __float_as_uint(As[buf][m + g    ][ks * 8 + q    ]);
                af[mi][1] = __float_as_uint(As[buf][m + g + 8][ks * 8 + q    ]);
                af[mi][2] = __float_as_uint(As[buf][m + g    ][ks * 8 + q + 4]);
                af[mi][3] = __float_as_uint(As[buf][m + g + 8][ks * 8 + q + 4]);
            }
            #pragma unroll
            for (int ni = 0; ni < NI; ni++) {
                int n = wn * (BN / 4) + ni * 8;
                bf[ni][0] = __float_as_uint(Bs[buf][ks * 8 + q    ][n + g]);
                bf[ni][1] = __float_as_uint(Bs[buf][ks * 8 + q + 4][n + g]);
            }
            #pragma unroll
            for (int mi = 0; mi < MI; mi++)
                #pragma unroll
                for (int ni = 0; ni < NI; ni++)
                    mma_tf32(acc[mi][ni], af[mi][0], af[mi][1], af[mi][2],
                             af[mi][3], bf[ni][0], bf[ni][1]);
        }
    };

    const int nIter = K / BK;
    loadA(0); loadB(0);
    storeA(0); storeB(0);
    __syncthreads();

    int buf = 0;
    for (int it = 0; it < nIter; it++) {
        if (it + 1 < nIter) { loadA((it + 1) * BK); loadB((it + 1) * BK); }
        compute(buf);
        if (it + 1 < nIter) {
            storeA(buf ^ 1); storeB(buf ^ 1);
            __syncthreads();
            buf ^= 1;
        }
    }

    // ---- epilogue ----
    auto emit = [&](int m, int n, float v0, float v1) {
        v0 *= alpha; v1 *= alpha;
        if (EPI == 1 || EPI == 2 || EPI == 3) { v0 += bias[n]; v1 += bias[n + 1]; }
        if (EPI == 2) { v0 = gelu_exact(v0); v1 = gelu_exact(v1); }
        float2* p = reinterpret_cast<float2*>(C + (size_t)m * ldc + n);
        if (EPI == 3) { float2 o = *p; v0 += o.x; v1 += o.y; }
        *p = make_float2(v0, v1);
    };

    #pragma unroll
    for (int mi = 0; mi < MI; mi++) {
        int m = m0 + wm * (BM / 2) + mi * 16 + g;
        #pragma unroll
        for (int ni = 0; ni < NI; ni++) {
            int n = n0 + wn * (BN / 4) + ni * 8 + q * 2;
            emit(m,     n, acc[mi][ni][0], acc[mi][ni][1]);
            emit(m + 8, n, acc[mi][ni][2], acc[mi][ni][3]);
        }
    }
}

// ---------------------------------------------------------------------------
// Host orchestration (graph-capturable: only kernel launches + async d2d copy)
// ---------------------------------------------------------------------------
extern "C" void kernel_launch(void* const* d_in, const int* in_sizes, int n_in,
                              void* d_out, int out_size)
{
    const float* x     = (const float*)d_in[0];
    const float* Wq    = (const float*)d_in[1];
    const float* Wk    = (const float*)d_in[2];
    const float* Wv    = (const float*)d_in[3];
    const float* Wo    = (const float*)d_in[4];
    const float* bo    = (const float*)d_in[5];
    const float* ln1g  = (const float*)d_in[6];
    const float* ln1b  = (const float*)d_in[7];
    const float* W1    = (const float*)d_in[8];
    const float* b1    = (const float*)d_in[9];
    const float* W2    = (const float*)d_in[10];
    const float* b2    = (const float*)d_in[11];
    const float* ln2g  = (const float*)d_in[12];
    const float* ln2b  = (const float*)d_in[13];

    float* h = (float*)d_out;

    float* scratch = nullptr;
    cudaGetSymbolAddress((void**)&scratch, g_scratch);
    float* y    = scratch + 0 * SZ_ACT;
    float* q    = scratch + 1 * SZ_ACT;
    float* kbuf = scratch + 2 * SZ_ACT;
    float* v    = scratch + 3 * SZ_ACT;
    float* tmp  = scratch + 4 * SZ_ACT;
    float* S    = scratch + 5 * SZ_ACT;

    // residual stream starts as x
    cudaMemcpyAsync(h, x, SZ_ACT * sizeof(float), cudaMemcpyDeviceToDevice, 0);

    const long long DD  = (long long)D_MODEL * D_MODEL;
    const long long sND = (long long)N_SEQ * D_MODEL;   // per-batch act stride
    const long long sNN = (long long)N_SEQ * N_SEQ;     // per-head S stride

    dim3 gProj(D_MODEL / 128, TOK / 128, 1);             // (4, 64)
    dim3 gScore(N_SEQ / 128, N_SEQ / 128, B_SZ*H_HEADS); // (16, 16, 32)
    dim3 gAV(1, N_SEQ / 128, B_SZ * H_HEADS);            // (1, 16, 32)

    for (int l = 0; l < L_LAYERS; l++) {
        const float* wq  = Wq + (size_t)l * DD;
        const float* wk  = Wk + (size_t)l * DD;
        const float* wv  = Wv + (size_t)l * DD;
        const float* wo  = Wo + (size_t)l * DD;
        const float* w1  = W1 + (size_t)l * DD;
        const float* w2  = W2 + (size_t)l * DD;
        const float* bo_ = bo + (size_t)l * D_MODEL;
        const float* b1_ = b1 + (size_t)l * D_MODEL;
        const float* b2_ = b2 + (size_t)l * D_MODEL;

        // y = LN1(h)
        ln_kernel<<<TOK, 128>>>(h, ln1g + (size_t)l*D_MODEL, ln1b + (size_t)l*D_MODEL, y);

        // q/k/v = y @ W{q,k,v}
        mma_gemm<128,128,false,0><<<gProj,256>>>(
            y, D_MODEL, 0, 0, wq, D_MODEL, 0, 0, q, D_MODEL, 0, 0, nullptr, D_MODEL, 1.0f);
        mma_gemm<128,128,false,0><<<gProj,256>>>(
            y, D_MODEL, 0, 0, wk, D_MODEL, 0, 0, kbuf, D_MODEL, 0, 0, nullptr, D_MODEL, 1.0f);
        mma_gemm<128,128,false,0><<<gProj,256>>>(
            y, D_MODEL, 0, 0, wv, D_MODEL, 0, 0, v, D_MODEL, 0, 0, nullptr, D_MODEL, 1.0f);

        // S = scale * q @ k^T   (batched over b,h)
        mma_gemm<128,128,true,0><<<gScore,256>>>(
            q,    D_MODEL, sND, HD_DIM,
            kbuf, D_MODEL, sND, HD_DIM,
            S,    N_SEQ,   (long long)H_HEADS * sNN, sNN,
            nullptr, HD_DIM, ATTN_SCALE);

        // softmax rows
        softmax_kernel<<<B_SZ*H_HEADS*N_SEQ, 256>>>(S);

        // tmp = S @ v
        mma_gemm<128,64,false,0><<<gAV,256>>>(
            S,   N_SEQ,   (long long)H_HEADS * sNN, sNN,
            v,   D_MODEL, sND, HD_DIM,
            tmp, D_MODEL, sND, HD_DIM,
            nullptr, N_SEQ, 1.0f);

        // h = h + tmp @ Wo + bo
        mma_gemm<128,128,false,3><<<gProj,256>>>(
            tmp, D_MODEL, 0, 0, wo, D_MODEL, 0, 0, h, D_MODEL, 0, 0, bo_, D_MODEL, 1.0f);

        // y = LN2(h)
        ln_kernel<<<TOK, 128>>>(h, ln2g + (size_t)l*D_MODEL, ln2b + (size_t)l*D_MODEL, y);

        // tmp = gelu(y @ W1 + b1)
        mma_gemm<128,128,false,2><<<gProj,256>>>(
            y, D_MODEL, 0, 0, w1, D_MODEL, 0, 0, tmp, D_MODEL, 0, 0, b1_, D_MODEL, 1.0f);

        // h = h + tmp @ W2 + b2
        mma_gemm<128,128,false,3><<<gProj,256>>>(
            tmp, D_MODEL, 0, 0, w2, D_MODEL, 0, 0, h, D_MODEL, 0, 0, b2_, D_MODEL, 1.0f);
    }
}